// round 1
// baseline (speedup 1.0000x reference)
#include <cuda_runtime.h>
#include <cuda_bf16.h>

#define DF 128
#define NMAX 50000
#define NCLS 10

// Scratch (allocation-free): ~77 MB of __device__ globals.
__device__ __align__(16) float g_support[(size_t)NMAX * DF];
__device__ __align__(16) float g_agg[(size_t)NMAX * DF];
__device__ __align__(16) float g_h[(size_t)NMAX * DF];
__device__ unsigned g_okey[3 * DF];

// Order-preserving float<->uint encoding for atomicMax on floats.
__device__ __forceinline__ unsigned fenc(float x) {
    unsigned u = __float_as_uint(x);
    return (u & 0x80000000u) ? ~u : (u | 0x80000000u);
}
__device__ __forceinline__ float fdec(unsigned k) {
    unsigned u = (k & 0x80000000u) ? (k & 0x7FFFFFFFu) : ~k;
    return __uint_as_float(u);
}

// C = A @ W   (A: [N,128], W: [128,128]); also zeroes g_agg and resets okey row.
// Tile: 64 rows/block, full K=128, full 128 cols. 256 threads.
// Dynamic smem: Ws 128*128 (64KB) + As 64*128 (32KB) = 96KB.
__global__ __launch_bounds__(256) void gemm_kernel(const float* __restrict__ A,
                                                   const float* __restrict__ W,
                                                   int N, int layer, int use_gh) {
    extern __shared__ float smem[];
    float* Ws = smem;              // [128][128]
    float* As = smem + DF * DF;    // [64][128]
    const float* Ain = use_gh ? g_h : A;

    int t = threadIdx.x;

    // Fold in agg zeroing (grid-stride) — runs before the scatter kernel.
    size_t total = (size_t)N * DF;
    for (size_t i = (size_t)blockIdx.x * 256 + t; i < total; i += (size_t)gridDim.x * 256)
        g_agg[i] = 0.0f;
    if (blockIdx.x == 0 && t < DF) g_okey[layer * DF + t] = 0u;

    for (int i = t; i < DF * DF; i += 256) Ws[i] = W[i];
    int r0 = blockIdx.x * 64;
    for (int i = t; i < 64 * DF; i += 256) {
        int r = r0 + (i >> 7);
        As[i] = (r < N) ? Ain[(size_t)r * DF + (i & 127)] : 0.0f;
    }
    __syncthreads();

    int tx = t & 31;   // column group: cols [tx*4, tx*4+4)
    int ty = t >> 5;   // row group: rows ty*8 .. ty*8+7
    float4 acc[8];
#pragma unroll
    for (int r = 0; r < 8; r++) acc[r] = make_float4(0.f, 0.f, 0.f, 0.f);

#pragma unroll 4
    for (int k = 0; k < DF; k++) {
        float4 wv = *(const float4*)&Ws[k * DF + tx * 4];
#pragma unroll
        for (int r = 0; r < 8; r++) {
            float a = As[(ty * 8 + r) * DF + k];
            acc[r].x += a * wv.x;
            acc[r].y += a * wv.y;
            acc[r].z += a * wv.z;
            acc[r].w += a * wv.w;
        }
    }

#pragma unroll
    for (int r = 0; r < 8; r++) {
        int row = r0 + ty * 8 + r;
        if (row < N) *(float4*)&g_support[(size_t)row * DF + tx * 4] = acc[r];
    }
}

// One warp per edge: gather support[src] (512B), scale by w, red.v4 into agg[dst].
__global__ __launch_bounds__(256) void scatter_kernel(const int* __restrict__ src,
                                                      const int* __restrict__ dst,
                                                      const float* __restrict__ w,
                                                      int E) {
    int lane = threadIdx.x & 31;
    int e = blockIdx.x * 8 + (threadIdx.x >> 5);
    if (e >= E) return;

    int s = 0, d = 0;
    float wt = 0.f;
    if (lane == 0) {
        s = src[e];
        d = dst[e];
        wt = w[e];
    }
    s = __shfl_sync(0xffffffffu, s, 0);
    d = __shfl_sync(0xffffffffu, d, 0);
    wt = __shfl_sync(0xffffffffu, wt, 0);

    const float4* sp = (const float4*)g_support;
    float4 v = sp[(size_t)s * 32 + lane];
    v.x *= wt; v.y *= wt; v.z *= wt; v.w *= wt;

    float* ap = g_agg + ((size_t)d * DF + lane * 4);
    asm volatile("red.global.add.v4.f32 [%0], {%1,%2,%3,%4};"
                 :: "l"(ap), "f"(v.x), "f"(v.y), "f"(v.z), "f"(v.w)
                 : "memory");
}

// Bias + (optional relu) + write h + column-max (one atomicMax per col per block).
__global__ __launch_bounds__(128) void epilogue_kernel(const float* __restrict__ b,
                                                       int N, int layer, int do_relu) {
    int d = threadIdx.x;
    float bias = b[d];
    int r0 = blockIdx.x * 256;
    int r1 = min(r0 + 256, N);
    float m = -3.402823466e+38f;
#pragma unroll 4
    for (int r = r0; r < r1; r++) {
        float v = g_agg[(size_t)r * DF + d] + bias;
        if (do_relu) {
            v = fmaxf(v, 0.0f);
            g_h[(size_t)r * DF + d] = v;
        }
        m = fmaxf(m, v);
    }
    atomicMax(&g_okey[layer * DF + d], fenc(m));
}

// Decode 3*128 col-maxes, 10x384 matvec + bias, log_softmax. Single tiny block.
__global__ __launch_bounds__(128) void final_kernel(const float* __restrict__ lin_W,
                                                    const float* __restrict__ lin_b,
                                                    float* __restrict__ out) {
    __shared__ float lin_in[3 * DF];
    __shared__ float logits[NCLS];
    int t = threadIdx.x;
    for (int i = t; i < 3 * DF; i += 128) lin_in[i] = fdec(g_okey[i]);
    __syncthreads();
    if (t < NCLS) {
        float s = lin_b[t];
#pragma unroll 4
        for (int j = 0; j < 3 * DF; j++) s += lin_W[t * 3 * DF + j] * lin_in[j];
        logits[t] = s;
    }
    __syncthreads();
    if (t == 0) {
        float m = -3.402823466e+38f;
        for (int c = 0; c < NCLS; c++) m = fmaxf(m, logits[c]);
        float se = 0.f;
        for (int c = 0; c < NCLS; c++) se += expf(logits[c] - m);
        float lse = m + logf(se);
        for (int c = 0; c < NCLS; c++) out[c] = logits[c] - lse;
    }
}

extern "C" void kernel_launch(void* const* d_in, const int* in_sizes, int n_in,
                              void* d_out, int out_size) {
    const float* x    = (const float*)d_in[0];
    const int*   esrc = (const int*)d_in[1];
    const int*   edst = (const int*)d_in[2];
    const float* ew   = (const float*)d_in[3];
    const float* W1   = (const float*)d_in[4];
    const float* b1   = (const float*)d_in[5];
    const float* W2   = (const float*)d_in[6];
    const float* b2   = (const float*)d_in[7];
    const float* W3   = (const float*)d_in[8];
    const float* b3   = (const float*)d_in[9];
    const float* linW = (const float*)d_in[10];
    const float* linb = (const float*)d_in[11];
    float* out = (float*)d_out;

    int N = in_sizes[0] / DF;
    int E = in_sizes[1];

    int gemm_blocks = (N + 63) / 64;
    int scat_blocks = (E + 7) / 8;
    int epi_blocks  = (N + 255) / 256;
    int gemm_smem = (DF * DF + 64 * DF) * (int)sizeof(float);  // 96KB

    static int smem_set = 0;
    if (!smem_set) {
        cudaFuncSetAttribute(gemm_kernel, cudaFuncAttributeMaxDynamicSharedMemorySize, gemm_smem);
        smem_set = 1;
    }

    // Layer 1
    gemm_kernel<<<gemm_blocks, 256, gemm_smem>>>(x, W1, N, 0, 0);
    scatter_kernel<<<scat_blocks, 256>>>(esrc, edst, ew, E);
    epilogue_kernel<<<epi_blocks, 128>>>(b1, N, 0, 1);
    // Layer 2
    gemm_kernel<<<gemm_blocks, 256, gemm_smem>>>(nullptr, W2, N, 1, 1);
    scatter_kernel<<<scat_blocks, 256>>>(esrc, edst, ew, E);
    epilogue_kernel<<<epi_blocks, 128>>>(b2, N, 1, 1);
    // Layer 3 (no relu, no h write)
    gemm_kernel<<<gemm_blocks, 256, gemm_smem>>>(nullptr, W3, N, 2, 1);
    scatter_kernel<<<scat_blocks, 256>>>(esrc, edst, ew, E);
    epilogue_kernel<<<epi_blocks, 128>>>(b3, N, 2, 0);
    // Head
    final_kernel<<<1, 128>>>(linW, linb, out);
}

// round 2
// speedup vs baseline: 1.6280x; 1.6280x over previous
#include <cuda_runtime.h>
#include <cuda_bf16.h>

#define DF 128
#define NMAX 50000
#define EMAX 800000
#define NCLS 10

// Scratch (allocation-free __device__ globals): ~58 MB.
__device__ __align__(16) float g_support[(size_t)NMAX * DF];
__device__ __align__(16) float g_h[(size_t)NMAX * DF];
__device__ __align__(16) int2  g_edge_s[EMAX];     // sorted-by-dst (src, bits(w))
__device__ int g_cnt[NMAX + 1];
__device__ int g_rowptr[NMAX + 1];
__device__ int g_cur[NMAX + 1];
__device__ unsigned g_okey[3 * DF];

// Order-preserving float<->uint encoding for max via atomicMax(u32).
__device__ __forceinline__ unsigned fenc(float x) {
    unsigned u = __float_as_uint(x);
    return (u & 0x80000000u) ? ~u : (u | 0x80000000u);
}
__device__ __forceinline__ float fdec(unsigned k) {
    unsigned u = (k & 0x80000000u) ? (k & 0x7FFFFFFFu) : ~k;
    return __uint_as_float(u);
}

// ---------------- sort: counting sort of edges by dst -------------------

__global__ __launch_bounds__(256) void init_kernel(int N) {
    int i = blockIdx.x * 256 + threadIdx.x;
    if (i <= N) g_cnt[i] = 0;
    if (i < 3 * DF) g_okey[i] = 0u;
}

__global__ __launch_bounds__(256) void hist_kernel(const int* __restrict__ dst, int E) {
    int e = blockIdx.x * 256 + threadIdx.x;
    if (e < E) atomicAdd(&g_cnt[dst[e]], 1);
}

// Single-block exclusive scan over g_cnt[0..N) -> g_rowptr/g_cur; g_rowptr[N]=E.
__global__ __launch_bounds__(1024) void scan_kernel(int N) {
    __shared__ int part[1024];
    __shared__ int carry[1024];
    int t = threadIdx.x;
    int chunk = (N + 1023) / 1024;
    int base = t * chunk;
    int s = 0;
    for (int j = 0; j < chunk; j++) {
        int idx = base + j;
        if (idx < N) s += g_cnt[idx];
    }
    part[t] = s;
    __syncthreads();
    // Hillis-Steele inclusive scan, then shift to exclusive.
    for (int off = 1; off < 1024; off <<= 1) {
        int v = part[t];
        int add = (t >= off) ? part[t - off] : 0;
        __syncthreads();
        part[t] = v + add;
        __syncthreads();
    }
    carry[t] = (t == 0) ? 0 : part[t - 1];
    __syncthreads();
    int run = carry[t];
    for (int j = 0; j < chunk; j++) {
        int idx = base + j;
        if (idx < N) {
            g_rowptr[idx] = run;
            g_cur[idx] = run;
            run += g_cnt[idx];
        }
    }
    if (base < N && base + chunk >= N) g_rowptr[N] = run;
}

__global__ __launch_bounds__(256) void reorder_kernel(const int* __restrict__ src,
                                                      const int* __restrict__ dst,
                                                      const float* __restrict__ w,
                                                      int E) {
    int e = blockIdx.x * 256 + threadIdx.x;
    if (e >= E) return;
    int d = dst[e];
    int pos = atomicAdd(&g_cur[d], 1);
    g_edge_s[pos] = make_int2(src[e], __float_as_int(w[e]));
}

// ---------------- GEMM: support = Ain @ W  (128x128 tile, 8x8/thread) ----

#define ASTRIDE 132
#define GEMM_SMEM ((DF * DF + 32 * ASTRIDE) * (int)sizeof(float))  // 82432 B

__global__ __launch_bounds__(256, 2) void gemm_kernel(const float* __restrict__ A,
                                                      const float* __restrict__ W,
                                                      int N, int use_gh) {
    extern __shared__ float smem[];
    float* Ws = smem;                 // [128][128]
    float* Asx = smem + DF * DF;      // [32][132] transposed A chunk
    const float* Ain = use_gh ? g_h : A;

    int t = threadIdx.x;
    int r0 = blockIdx.x * 128;

    // Load full W (64KB) once.
    {
        const float4* Wv = (const float4*)W;
        float4* Wsv = (float4*)Ws;
        for (int i = t; i < DF * DF / 4; i += 256) Wsv[i] = Wv[i];
    }

    int tx = t & 15;   // cols tx*8 .. +7
    int ty = t >> 4;   // rows ty*8 .. +7
    float4 acc[8][2];
#pragma unroll
    for (int r = 0; r < 8; r++) {
        acc[r][0] = make_float4(0.f, 0.f, 0.f, 0.f);
        acc[r][1] = make_float4(0.f, 0.f, 0.f, 0.f);
    }

    int lslot = t & 7;    // which float4 (4 k's) within the 32-k chunk
    int lrow0 = t >> 3;   // 0..31; loads rows lrow0 + {0,32,64,96}

    for (int kc = 0; kc < 4; kc++) {
        __syncthreads();
        // Load A chunk [128 rows][32 k] transposed into Asx[kk][row].
#pragma unroll
        for (int rp = 0; rp < 4; rp++) {
            int row = lrow0 + rp * 32;
            int gr = r0 + row;
            float4 av = make_float4(0.f, 0.f, 0.f, 0.f);
            if (gr < N) av = *(const float4*)&Ain[(size_t)gr * DF + kc * 32 + lslot * 4];
            Asx[(lslot * 4 + 0) * ASTRIDE + row] = av.x;
            Asx[(lslot * 4 + 1) * ASTRIDE + row] = av.y;
            Asx[(lslot * 4 + 2) * ASTRIDE + row] = av.z;
            Asx[(lslot * 4 + 3) * ASTRIDE + row] = av.w;
        }
        __syncthreads();

#pragma unroll 8
        for (int kk = 0; kk < 32; kk++) {
            int k = kc * 32 + kk;
            float4 w0 = *(const float4*)&Ws[k * DF + tx * 8];
            float4 w1 = *(const float4*)&Ws[k * DF + tx * 8 + 4];
            float4 a0 = *(const float4*)&Asx[kk * ASTRIDE + ty * 8];
            float4 a1 = *(const float4*)&Asx[kk * ASTRIDE + ty * 8 + 4];
            float aa[8] = {a0.x, a0.y, a0.z, a0.w, a1.x, a1.y, a1.z, a1.w};
#pragma unroll
            for (int r = 0; r < 8; r++) {
                acc[r][0].x += aa[r] * w0.x;
                acc[r][0].y += aa[r] * w0.y;
                acc[r][0].z += aa[r] * w0.z;
                acc[r][0].w += aa[r] * w0.w;
                acc[r][1].x += aa[r] * w1.x;
                acc[r][1].y += aa[r] * w1.y;
                acc[r][1].z += aa[r] * w1.z;
                acc[r][1].w += aa[r] * w1.w;
            }
        }
    }

#pragma unroll
    for (int r = 0; r < 8; r++) {
        int row = r0 + ty * 8 + r;
        if (row < N) {
            *(float4*)&g_support[(size_t)row * DF + tx * 8] = acc[r][0];
            *(float4*)&g_support[(size_t)row * DF + tx * 8 + 4] = acc[r][1];
        }
    }
}

// ---------------- segment-sum + bias (+relu, h write) + column max --------
// One warp per dst row; 8 rows per block. No atomics on the feature data.

__global__ __launch_bounds__(256) void seg_kernel(const float* __restrict__ b,
                                                  int N, int layer, int do_relu) {
    __shared__ unsigned smax[DF];
    int t = threadIdx.x;
    int lane = t & 31;
    int wrp = t >> 5;
    if (t < DF) smax[t] = 0u;
    __syncthreads();

    int d = blockIdx.x * 8 + wrp;
    if (d < N) {
        int beg = g_rowptr[d];
        int end = g_rowptr[d + 1];
        const float4* sup = (const float4*)g_support;

        float4 acc0 = make_float4(0.f, 0.f, 0.f, 0.f);
        float4 acc1 = make_float4(0.f, 0.f, 0.f, 0.f);
        int i = beg;
        for (; i + 2 <= end; i += 2) {
            int2 e0 = g_edge_s[i];
            int2 e1 = g_edge_s[i + 1];
            float4 v0 = sup[(size_t)e0.x * 32 + lane];
            float4 v1 = sup[(size_t)e1.x * 32 + lane];
            float w0 = __int_as_float(e0.y);
            float w1 = __int_as_float(e1.y);
            acc0.x += v0.x * w0; acc0.y += v0.y * w0;
            acc0.z += v0.z * w0; acc0.w += v0.w * w0;
            acc1.x += v1.x * w1; acc1.y += v1.y * w1;
            acc1.z += v1.z * w1; acc1.w += v1.w * w1;
        }
        if (i < end) {
            int2 e0 = g_edge_s[i];
            float4 v0 = sup[(size_t)e0.x * 32 + lane];
            float w0 = __int_as_float(e0.y);
            acc0.x += v0.x * w0; acc0.y += v0.y * w0;
            acc0.z += v0.z * w0; acc0.w += v0.w * w0;
        }
        float4 v;
        const float4* bb = (const float4*)b;
        float4 bv = bb[lane];
        v.x = acc0.x + acc1.x + bv.x;
        v.y = acc0.y + acc1.y + bv.y;
        v.z = acc0.z + acc1.z + bv.z;
        v.w = acc0.w + acc1.w + bv.w;
        if (do_relu) {
            v.x = fmaxf(v.x, 0.f); v.y = fmaxf(v.y, 0.f);
            v.z = fmaxf(v.z, 0.f); v.w = fmaxf(v.w, 0.f);
            *(float4*)&g_h[(size_t)d * DF + lane * 4] = v;
        }
        atomicMax(&smax[lane * 4 + 0], fenc(v.x));
        atomicMax(&smax[lane * 4 + 1], fenc(v.y));
        atomicMax(&smax[lane * 4 + 2], fenc(v.z));
        atomicMax(&smax[lane * 4 + 3], fenc(v.w));
    }
    __syncthreads();
    if (t < DF) atomicMax(&g_okey[layer * DF + t], smax[t]);
}

// ---------------- head: decode maxes, 10x384 matvec, log_softmax ----------

__global__ __launch_bounds__(128) void final_kernel(const float* __restrict__ lin_W,
                                                    const float* __restrict__ lin_b,
                                                    float* __restrict__ out) {
    __shared__ float lin_in[3 * DF];
    __shared__ float logits[NCLS];
    int t = threadIdx.x;
    for (int i = t; i < 3 * DF; i += 128) lin_in[i] = fdec(g_okey[i]);
    __syncthreads();
    if (t < NCLS) {
        float s = lin_b[t];
#pragma unroll 4
        for (int j = 0; j < 3 * DF; j++) s += lin_W[t * 3 * DF + j] * lin_in[j];
        logits[t] = s;
    }
    __syncthreads();
    if (t == 0) {
        float m = -3.402823466e+38f;
        for (int c = 0; c < NCLS; c++) m = fmaxf(m, logits[c]);
        float se = 0.f;
        for (int c = 0; c < NCLS; c++) se += expf(logits[c] - m);
        float lse = m + logf(se);
        for (int c = 0; c < NCLS; c++) out[c] = logits[c] - lse;
    }
}

extern "C" void kernel_launch(void* const* d_in, const int* in_sizes, int n_in,
                              void* d_out, int out_size) {
    const float* x    = (const float*)d_in[0];
    const int*   esrc = (const int*)d_in[1];
    const int*   edst = (const int*)d_in[2];
    const float* ew   = (const float*)d_in[3];
    const float* W1   = (const float*)d_in[4];
    const float* b1   = (const float*)d_in[5];
    const float* W2   = (const float*)d_in[6];
    const float* b2   = (const float*)d_in[7];
    const float* W3   = (const float*)d_in[8];
    const float* b3   = (const float*)d_in[9];
    const float* linW = (const float*)d_in[10];
    const float* linb = (const float*)d_in[11];
    float* out = (float*)d_out;

    int N = in_sizes[0] / DF;
    int E = in_sizes[1];

    cudaFuncSetAttribute(gemm_kernel, cudaFuncAttributeMaxDynamicSharedMemorySize, GEMM_SMEM);

    int eb = (E + 255) / 256;
    int gemm_blocks = (N + 127) / 128;
    int seg_blocks = (N + 7) / 8;

    // One-time (per launch) edge sort by dst.
    init_kernel<<<(N + 256) / 256, 256>>>(N);
    hist_kernel<<<eb, 256>>>(edst, E);
    scan_kernel<<<1, 1024>>>(N);
    reorder_kernel<<<eb, 256>>>(esrc, edst, ew, E);

    // Layer 1
    gemm_kernel<<<gemm_blocks, 256, GEMM_SMEM>>>(x, W1, N, 0);
    seg_kernel<<<seg_blocks, 256>>>(b1, N, 0, 1);
    // Layer 2
    gemm_kernel<<<gemm_blocks, 256, GEMM_SMEM>>>(nullptr, W2, N, 1);
    seg_kernel<<<seg_blocks, 256>>>(b2, N, 1, 1);
    // Layer 3 (no relu, no h write)
    gemm_kernel<<<gemm_blocks, 256, GEMM_SMEM>>>(nullptr, W3, N, 2);
    seg_kernel<<<seg_blocks, 256>>>(b3, N, 2, 0);
    // Head
    final_kernel<<<1, 128>>>(linW, linb, out);
}

// round 3
// speedup vs baseline: 2.1187x; 1.3014x over previous
#include <cuda_runtime.h>
#include <cuda_bf16.h>

#define DF 128
#define NMAX 50000
#define EMAX 800000
#define NCLS 10

// Scratch (allocation-free __device__ globals): ~58 MB.
__device__ __align__(16) float g_support[(size_t)NMAX * DF];
__device__ __align__(16) float g_h[(size_t)NMAX * DF];
__device__ __align__(16) int2  g_edge_s[EMAX];     // sorted-by-dst (src, bits(w))
__device__ int g_cnt[NMAX + 1];
__device__ int g_rowptr[NMAX + 1];
__device__ int g_cur[NMAX + 1];
__device__ unsigned g_okey[3 * DF];

__device__ __forceinline__ unsigned fenc(float x) {
    unsigned u = __float_as_uint(x);
    return (u & 0x80000000u) ? ~u : (u | 0x80000000u);
}
__device__ __forceinline__ float fdec(unsigned k) {
    unsigned u = (k & 0x80000000u) ? (k & 0x7FFFFFFFu) : ~k;
    return __uint_as_float(u);
}
__device__ __forceinline__ unsigned f2tf(float x) {
    unsigned r;
    asm("cvt.rna.tf32.f32 %0, %1;" : "=r"(r) : "f"(x));
    return r;
}

// ---------------- sort: counting sort of edges by dst -------------------

__global__ __launch_bounds__(256) void init_kernel(int N) {
    int i = blockIdx.x * 256 + threadIdx.x;
    if (i <= N) g_cnt[i] = 0;
    if (i < 3 * DF) g_okey[i] = 0u;
}

__global__ __launch_bounds__(256) void hist_kernel(const int* __restrict__ dst, int E) {
    int e = blockIdx.x * 256 + threadIdx.x;
    if (e < E) atomicAdd(&g_cnt[dst[e]], 1);
}

__global__ __launch_bounds__(1024) void scan_kernel(int N) {
    __shared__ int part[1024];
    __shared__ int carry[1024];
    int t = threadIdx.x;
    int chunk = (N + 1023) / 1024;
    int base = t * chunk;
    int s = 0;
    for (int j = 0; j < chunk; j++) {
        int idx = base + j;
        if (idx < N) s += g_cnt[idx];
    }
    part[t] = s;
    __syncthreads();
    for (int off = 1; off < 1024; off <<= 1) {
        int v = part[t];
        int add = (t >= off) ? part[t - off] : 0;
        __syncthreads();
        part[t] = v + add;
        __syncthreads();
    }
    carry[t] = (t == 0) ? 0 : part[t - 1];
    __syncthreads();
    int run = carry[t];
    for (int j = 0; j < chunk; j++) {
        int idx = base + j;
        if (idx < N) {
            g_rowptr[idx] = run;
            g_cur[idx] = run;
            run += g_cnt[idx];
        }
    }
    if (base < N && base + chunk >= N) g_rowptr[N] = run;
}

__global__ __launch_bounds__(256) void reorder_kernel(const int* __restrict__ src,
                                                      const int* __restrict__ dst,
                                                      const float* __restrict__ w,
                                                      int E) {
    int e = blockIdx.x * 256 + threadIdx.x;
    if (e >= E) return;
    int d = dst[e];
    int pos = atomicAdd(&g_cur[d], 1);
    g_edge_s[pos] = make_int2(src[e], __float_as_int(w[e]));
}

// ---------------- GEMM: support = Ain @ W via TF32 mma.sync ----------------
// Block tile 128x128. 8 warps in 4(m) x 2(n) grid; warp tile 32x64
// = 2 m-tiles x 8 n-tiles of m16n8k8. Full K=128 in two 64-wide chunks.

#define SW 136
#define SA 68
#define GEMM_SMEM ((DF * SW + DF * SA) * (int)sizeof(unsigned))  // 104448 B

__global__ __launch_bounds__(256, 2) void gemm_kernel(const float* __restrict__ A,
                                                      const float* __restrict__ W,
                                                      int N, int use_gh) {
    extern __shared__ unsigned smem_u[];
    unsigned* Ws = smem_u;            // [128][136] tf32
    unsigned* As = smem_u + DF * SW;  // [128][68] tf32 (k-chunk of 64)
    const float* Ain = use_gh ? g_h : A;

    int t = threadIdx.x;
    int lane = t & 31;
    int wrp = t >> 5;
    int wm = wrp >> 1;        // 0..3
    int wn = wrp & 1;         // 0..1
    int r0 = blockIdx.x * 128;

    // Stage W (tf32), conflict-free stride 136.
    for (int i = t; i < DF * DF / 4; i += 256) {
        int k = i >> 5;          // 32 float4 per row
        int n4 = (i & 31) * 4;
        float4 wv = *(const float4*)&W[k * DF + n4];
        Ws[k * SW + n4 + 0] = f2tf(wv.x);
        Ws[k * SW + n4 + 1] = f2tf(wv.y);
        Ws[k * SW + n4 + 2] = f2tf(wv.z);
        Ws[k * SW + n4 + 3] = f2tf(wv.w);
    }

    float acc[2][8][4];
#pragma unroll
    for (int mt = 0; mt < 2; mt++)
#pragma unroll
        for (int nt = 0; nt < 8; nt++)
#pragma unroll
            for (int r = 0; r < 4; r++) acc[mt][nt][r] = 0.f;

    int gid = lane >> 2;      // group id 0..7
    int tig = lane & 3;       // thread in group 0..3

    for (int kc = 0; kc < 2; kc++) {
        __syncthreads();
        // Stage A chunk [128 rows][64 k] as tf32, stride 68.
        for (int i = t; i < DF * 16; i += 256) {   // 16 float4 per row
            int row = i >> 4;
            int k4 = (i & 15) * 4;
            int gr = r0 + row;
            float4 av = make_float4(0.f, 0.f, 0.f, 0.f);
            if (gr < N) av = *(const float4*)&Ain[(size_t)gr * DF + kc * 64 + k4];
            As[row * SA + k4 + 0] = f2tf(av.x);
            As[row * SA + k4 + 1] = f2tf(av.y);
            As[row * SA + k4 + 2] = f2tf(av.z);
            As[row * SA + k4 + 3] = f2tf(av.w);
        }
        __syncthreads();

#pragma unroll
        for (int kk = 0; kk < 8; kk++) {
            int kb = kk * 8;            // chunk-local k base
            int kg = kc * 64 + kb;      // global k base (for Ws)
            unsigned afr[2][4];
#pragma unroll
            for (int mt = 0; mt < 2; mt++) {
                int arow = wm * 32 + mt * 16 + gid;
                afr[mt][0] = As[arow * SA + kb + tig];
                afr[mt][1] = As[(arow + 8) * SA + kb + tig];
                afr[mt][2] = As[arow * SA + kb + tig + 4];
                afr[mt][3] = As[(arow + 8) * SA + kb + tig + 4];
            }
#pragma unroll
            for (int nt = 0; nt < 8; nt++) {
                int ncol = wn * 64 + nt * 8 + gid;
                unsigned b0 = Ws[(kg + tig) * SW + ncol];
                unsigned b1 = Ws[(kg + tig + 4) * SW + ncol];
#pragma unroll
                for (int mt = 0; mt < 2; mt++) {
                    asm volatile(
                        "mma.sync.aligned.m16n8k8.row.col.f32.tf32.tf32.f32 "
                        "{%0,%1,%2,%3}, {%4,%5,%6,%7}, {%8,%9}, {%0,%1,%2,%3};"
                        : "+f"(acc[mt][nt][0]), "+f"(acc[mt][nt][1]),
                          "+f"(acc[mt][nt][2]), "+f"(acc[mt][nt][3])
                        : "r"(afr[mt][0]), "r"(afr[mt][1]),
                          "r"(afr[mt][2]), "r"(afr[mt][3]),
                          "r"(b0), "r"(b1));
                }
            }
        }
    }

    // Write out. c0,c1 = (row, 2*tig), (row, 2*tig+1); c2,c3 at row+8.
#pragma unroll
    for (int mt = 0; mt < 2; mt++) {
#pragma unroll
        for (int nt = 0; nt < 8; nt++) {
            int row = r0 + wm * 32 + mt * 16 + gid;
            int col = wn * 64 + nt * 8 + 2 * tig;
            if (row < N)
                *(float2*)&g_support[(size_t)row * DF + col] =
                    make_float2(acc[mt][nt][0], acc[mt][nt][1]);
            if (row + 8 < N)
                *(float2*)&g_support[(size_t)(row + 8) * DF + col] =
                    make_float2(acc[mt][nt][2], acc[mt][nt][3]);
        }
    }
}

// ---------------- segment-sum + bias (+relu, h write) + column max --------
// One warp per dst row; 4-deep gather pipeline, two accumulator chains.

__global__ __launch_bounds__(256) void seg_kernel(const float* __restrict__ b,
                                                  int N, int layer, int do_relu) {
    __shared__ unsigned smax[DF];
    int t = threadIdx.x;
    int lane = t & 31;
    int wrp = t >> 5;
    if (t < DF) smax[t] = 0u;
    __syncthreads();

    int d = blockIdx.x * 8 + wrp;
    if (d < N) {
        int beg = g_rowptr[d];
        int end = g_rowptr[d + 1];
        const float4* sup = (const float4*)g_support;

        float4 acc0 = make_float4(0.f, 0.f, 0.f, 0.f);
        float4 acc1 = make_float4(0.f, 0.f, 0.f, 0.f);
        int i = beg;
        for (; i + 4 <= end; i += 4) {
            int2 e0 = g_edge_s[i];
            int2 e1 = g_edge_s[i + 1];
            int2 e2 = g_edge_s[i + 2];
            int2 e3 = g_edge_s[i + 3];
            float4 v0 = sup[(size_t)e0.x * 32 + lane];
            float4 v1 = sup[(size_t)e1.x * 32 + lane];
            float4 v2 = sup[(size_t)e2.x * 32 + lane];
            float4 v3 = sup[(size_t)e3.x * 32 + lane];
            float w0 = __int_as_float(e0.y);
            float w1 = __int_as_float(e1.y);
            float w2 = __int_as_float(e2.y);
            float w3 = __int_as_float(e3.y);
            acc0.x += v0.x * w0; acc0.y += v0.y * w0;
            acc0.z += v0.z * w0; acc0.w += v0.w * w0;
            acc1.x += v1.x * w1; acc1.y += v1.y * w1;
            acc1.z += v1.z * w1; acc1.w += v1.w * w1;
            acc0.x += v2.x * w2; acc0.y += v2.y * w2;
            acc0.z += v2.z * w2; acc0.w += v2.w * w2;
            acc1.x += v3.x * w3; acc1.y += v3.y * w3;
            acc1.z += v3.z * w3; acc1.w += v3.w * w3;
        }
        for (; i < end; i++) {
            int2 e0 = g_edge_s[i];
            float4 v0 = sup[(size_t)e0.x * 32 + lane];
            float w0 = __int_as_float(e0.y);
            acc0.x += v0.x * w0; acc0.y += v0.y * w0;
            acc0.z += v0.z * w0; acc0.w += v0.w * w0;
        }
        float4 v;
        const float4* bb = (const float4*)b;
        float4 bv = bb[lane];
        v.x = acc0.x + acc1.x + bv.x;
        v.y = acc0.y + acc1.y + bv.y;
        v.z = acc0.z + acc1.z + bv.z;
        v.w = acc0.w + acc1.w + bv.w;
        if (do_relu) {
            v.x = fmaxf(v.x, 0.f); v.y = fmaxf(v.y, 0.f);
            v.z = fmaxf(v.z, 0.f); v.w = fmaxf(v.w, 0.f);
            *(float4*)&g_h[(size_t)d * DF + lane * 4] = v;
        }
        atomicMax(&smax[lane * 4 + 0], fenc(v.x));
        atomicMax(&smax[lane * 4 + 1], fenc(v.y));
        atomicMax(&smax[lane * 4 + 2], fenc(v.z));
        atomicMax(&smax[lane * 4 + 3], fenc(v.w));
    }
    __syncthreads();
    if (t < DF) atomicMax(&g_okey[layer * DF + t], smax[t]);
}

// ---------------- head ----------------------------------------------------

__global__ __launch_bounds__(128) void final_kernel(const float* __restrict__ lin_W,
                                                    const float* __restrict__ lin_b,
                                                    float* __restrict__ out) {
    __shared__ float lin_in[3 * DF];
    __shared__ float logits[NCLS];
    int t = threadIdx.x;
    for (int i = t; i < 3 * DF; i += 128) lin_in[i] = fdec(g_okey[i]);
    __syncthreads();
    if (t < NCLS) {
        float s = lin_b[t];
#pragma unroll 4
        for (int j = 0; j < 3 * DF; j++) s += lin_W[t * 3 * DF + j] * lin_in[j];
        logits[t] = s;
    }
    __syncthreads();
    if (t == 0) {
        float m = -3.402823466e+38f;
        for (int c = 0; c < NCLS; c++) m = fmaxf(m, logits[c]);
        float se = 0.f;
        for (int c = 0; c < NCLS; c++) se += expf(logits[c] - m);
        float lse = m + logf(se);
        for (int c = 0; c < NCLS; c++) out[c] = logits[c] - lse;
    }
}

extern "C" void kernel_launch(void* const* d_in, const int* in_sizes, int n_in,
                              void* d_out, int out_size) {
    const float* x    = (const float*)d_in[0];
    const int*   esrc = (const int*)d_in[1];
    const int*   edst = (const int*)d_in[2];
    const float* ew   = (const float*)d_in[3];
    const float* W1   = (const float*)d_in[4];
    const float* b1   = (const float*)d_in[5];
    const float* W2   = (const float*)d_in[6];
    const float* b2   = (const float*)d_in[7];
    const float* W3   = (const float*)d_in[8];
    const float* b3   = (const float*)d_in[9];
    const float* linW = (const float*)d_in[10];
    const float* linb = (const float*)d_in[11];
    float* out = (float*)d_out;

    int N = in_sizes[0] / DF;
    int E = in_sizes[1];

    static int attr_set = 0;
    if (!attr_set) {
        cudaFuncSetAttribute(gemm_kernel, cudaFuncAttributeMaxDynamicSharedMemorySize, GEMM_SMEM);
        attr_set = 1;
    }

    int eb = (E + 255) / 256;
    int gemm_blocks = (N + 127) / 128;
    int seg_blocks = (N + 7) / 8;

    init_kernel<<<(N + 256) / 256, 256>>>(N);
    hist_kernel<<<eb, 256>>>(edst, E);
    scan_kernel<<<1, 1024>>>(N);
    reorder_kernel<<<eb, 256>>>(esrc, edst, ew, E);

    gemm_kernel<<<gemm_blocks, 256, GEMM_SMEM>>>(x, W1, N, 0);
    seg_kernel<<<seg_blocks, 256>>>(b1, N, 0, 1);
    gemm_kernel<<<gemm_blocks, 256, GEMM_SMEM>>>(nullptr, W2, N, 1);
    seg_kernel<<<seg_blocks, 256>>>(b2, N, 1, 1);
    gemm_kernel<<<gemm_blocks, 256, GEMM_SMEM>>>(nullptr, W3, N, 2);
    seg_kernel<<<seg_blocks, 256>>>(b3, N, 2, 0);
    final_kernel<<<1, 128>>>(linW, linb, out);
}

// round 4
// speedup vs baseline: 2.2491x; 1.0616x over previous
#include <cuda_runtime.h>
#include <cuda_fp16.h>
#include <cuda_bf16.h>

#define DF 128
#define NMAX 50000
#define EMAX 800000
#define NCLS 10

// Scratch (allocation-free __device__ globals).
__device__ __align__(16) __half g_support[(size_t)NMAX * DF];   // fp16 gather source
__device__ __align__(16) float  g_h[(size_t)NMAX * DF];         // fp32 layer activations
__device__ __align__(16) int2   g_edge_s[EMAX];                 // sorted-by-dst (src, bits(w))
__device__ int g_cnt[NMAX + 1];
__device__ int g_rowptr[NMAX + 1];
__device__ int g_cur[NMAX + 1];
__device__ unsigned g_okey[3 * DF];

__device__ __forceinline__ unsigned fenc(float x) {
    unsigned u = __float_as_uint(x);
    return (u & 0x80000000u) ? ~u : (u | 0x80000000u);
}
__device__ __forceinline__ float fdec(unsigned k) {
    unsigned u = (k & 0x80000000u) ? (k & 0x7FFFFFFFu) : ~k;
    return __uint_as_float(u);
}
__device__ __forceinline__ unsigned f2tf(float x) {
    unsigned r;
    asm("cvt.rna.tf32.f32 %0, %1;" : "=r"(r) : "f"(x));
    return r;
}

// ---------------- sort: counting sort of edges by dst -------------------

__global__ __launch_bounds__(256) void init_kernel(int N) {
    int i = blockIdx.x * 256 + threadIdx.x;
    if (i <= N) g_cnt[i] = 0;
    if (i < 3 * DF) g_okey[i] = 0u;
}

__global__ __launch_bounds__(256) void hist_kernel(const int* __restrict__ dst, int E) {
    int e = blockIdx.x * 256 + threadIdx.x;
    if (e < E) atomicAdd(&g_cnt[dst[e]], 1);
}

__global__ __launch_bounds__(1024) void scan_kernel(int N) {
    __shared__ int part[1024];
    __shared__ int carry[1024];
    int t = threadIdx.x;
    int chunk = (N + 1023) / 1024;
    int base = t * chunk;
    int s = 0;
    for (int j = 0; j < chunk; j++) {
        int idx = base + j;
        if (idx < N) s += g_cnt[idx];
    }
    part[t] = s;
    __syncthreads();
    for (int off = 1; off < 1024; off <<= 1) {
        int v = part[t];
        int add = (t >= off) ? part[t - off] : 0;
        __syncthreads();
        part[t] = v + add;
        __syncthreads();
    }
    carry[t] = (t == 0) ? 0 : part[t - 1];
    __syncthreads();
    int run = carry[t];
    for (int j = 0; j < chunk; j++) {
        int idx = base + j;
        if (idx < N) {
            g_rowptr[idx] = run;
            g_cur[idx] = run;
            run += g_cnt[idx];
        }
    }
    if (base < N && base + chunk >= N) g_rowptr[N] = run;
}

__global__ __launch_bounds__(256) void reorder_kernel(const int* __restrict__ src,
                                                      const int* __restrict__ dst,
                                                      const float* __restrict__ w,
                                                      int E) {
    int e = blockIdx.x * 256 + threadIdx.x;
    if (e >= E) return;
    int d = dst[e];
    int pos = atomicAdd(&g_cur[d], 1);
    g_edge_s[pos] = make_int2(src[e], __float_as_int(w[e]));
}

// ---------------- GEMM: support(fp16) = Ain(fp32) @ W via TF32 mma.sync ----
// Block tile 128x128. 8 warps 4(m)x2(n); warp tile 32x64 = 2x8 m16n8k8 tiles.

#define SW 136
#define SA 68
#define GEMM_SMEM ((DF * SW + DF * SA) * (int)sizeof(unsigned))  // 104448 B

__global__ __launch_bounds__(256, 2) void gemm_kernel(const float* __restrict__ A,
                                                      const float* __restrict__ W,
                                                      int N, int use_gh) {
    extern __shared__ unsigned smem_u[];
    unsigned* Ws = smem_u;            // [128][136] tf32
    unsigned* As = smem_u + DF * SW;  // [128][68] tf32 (k-chunk of 64)
    const float* Ain = use_gh ? g_h : A;

    int t = threadIdx.x;
    int lane = t & 31;
    int wrp = t >> 5;
    int wm = wrp >> 1;
    int wn = wrp & 1;
    int r0 = blockIdx.x * 128;

    for (int i = t; i < DF * DF / 4; i += 256) {
        int k = i >> 5;
        int n4 = (i & 31) * 4;
        float4 wv = *(const float4*)&W[k * DF + n4];
        Ws[k * SW + n4 + 0] = f2tf(wv.x);
        Ws[k * SW + n4 + 1] = f2tf(wv.y);
        Ws[k * SW + n4 + 2] = f2tf(wv.z);
        Ws[k * SW + n4 + 3] = f2tf(wv.w);
    }

    float acc[2][8][4];
#pragma unroll
    for (int mt = 0; mt < 2; mt++)
#pragma unroll
        for (int nt = 0; nt < 8; nt++)
#pragma unroll
            for (int r = 0; r < 4; r++) acc[mt][nt][r] = 0.f;

    int gid = lane >> 2;
    int tig = lane & 3;

    for (int kc = 0; kc < 2; kc++) {
        __syncthreads();
        for (int i = t; i < DF * 16; i += 256) {
            int row = i >> 4;
            int k4 = (i & 15) * 4;
            int gr = r0 + row;
            float4 av = make_float4(0.f, 0.f, 0.f, 0.f);
            if (gr < N) av = *(const float4*)&Ain[(size_t)gr * DF + kc * 64 + k4];
            As[row * SA + k4 + 0] = f2tf(av.x);
            As[row * SA + k4 + 1] = f2tf(av.y);
            As[row * SA + k4 + 2] = f2tf(av.z);
            As[row * SA + k4 + 3] = f2tf(av.w);
        }
        __syncthreads();

#pragma unroll
        for (int kk = 0; kk < 8; kk++) {
            int kb = kk * 8;
            int kg = kc * 64 + kb;
            unsigned afr[2][4];
#pragma unroll
            for (int mt = 0; mt < 2; mt++) {
                int arow = wm * 32 + mt * 16 + gid;
                afr[mt][0] = As[arow * SA + kb + tig];
                afr[mt][1] = As[(arow + 8) * SA + kb + tig];
                afr[mt][2] = As[arow * SA + kb + tig + 4];
                afr[mt][3] = As[(arow + 8) * SA + kb + tig + 4];
            }
#pragma unroll
            for (int nt = 0; nt < 8; nt++) {
                int ncol = wn * 64 + nt * 8 + gid;
                unsigned b0 = Ws[(kg + tig) * SW + ncol];
                unsigned b1 = Ws[(kg + tig + 4) * SW + ncol];
#pragma unroll
                for (int mt = 0; mt < 2; mt++) {
                    asm volatile(
                        "mma.sync.aligned.m16n8k8.row.col.f32.tf32.tf32.f32 "
                        "{%0,%1,%2,%3}, {%4,%5,%6,%7}, {%8,%9}, {%0,%1,%2,%3};"
                        : "+f"(acc[mt][nt][0]), "+f"(acc[mt][nt][1]),
                          "+f"(acc[mt][nt][2]), "+f"(acc[mt][nt][3])
                        : "r"(afr[mt][0]), "r"(afr[mt][1]),
                          "r"(afr[mt][2]), "r"(afr[mt][3]),
                          "r"(b0), "r"(b1));
                }
            }
        }
    }

    // Write out as fp16 pairs: c0,c1 -> (row, 2*tig*? ) per mma fragment map.
#pragma unroll
    for (int mt = 0; mt < 2; mt++) {
#pragma unroll
        for (int nt = 0; nt < 8; nt++) {
            int row = r0 + wm * 32 + mt * 16 + gid;
            int col = wn * 64 + nt * 8 + 2 * tig;
            if (row < N)
                *(__half2*)&g_support[(size_t)row * DF + col] =
                    __floats2half2_rn(acc[mt][nt][0], acc[mt][nt][1]);
            if (row + 8 < N)
                *(__half2*)&g_support[(size_t)(row + 8) * DF + col] =
                    __floats2half2_rn(acc[mt][nt][2], acc[mt][nt][3]);
        }
    }
}

// ---------------- segment-sum + bias (+relu, h write) + column max --------
// One warp per dst row; fp16 gather (256B/row), fp32 accumulate.

__global__ __launch_bounds__(256) void seg_kernel(const float* __restrict__ b,
                                                  int N, int layer, int do_relu) {
    __shared__ unsigned smax[DF];
    int t = threadIdx.x;
    int lane = t & 31;
    int wrp = t >> 5;
    if (t < DF) smax[t] = 0u;
    __syncthreads();

    int d = blockIdx.x * 8 + wrp;
    if (d < N) {
        int beg = g_rowptr[d];
        int end = g_rowptr[d + 1];
        const uint2* sup = (const uint2*)g_support;   // 32 uint2 per row

        float4 acc0 = make_float4(0.f, 0.f, 0.f, 0.f);
        float4 acc1 = make_float4(0.f, 0.f, 0.f, 0.f);
        int i = beg;
        for (; i + 4 <= end; i += 4) {
            int2 e0 = g_edge_s[i];
            int2 e1 = g_edge_s[i + 1];
            int2 e2 = g_edge_s[i + 2];
            int2 e3 = g_edge_s[i + 3];
            uint2 u0 = sup[(size_t)e0.x * 32 + lane];
            uint2 u1 = sup[(size_t)e1.x * 32 + lane];
            uint2 u2 = sup[(size_t)e2.x * 32 + lane];
            uint2 u3 = sup[(size_t)e3.x * 32 + lane];
            float w0 = __int_as_float(e0.y);
            float w1 = __int_as_float(e1.y);
            float w2 = __int_as_float(e2.y);
            float w3 = __int_as_float(e3.y);
            float2 a0 = __half22float2(*(__half2*)&u0.x);
            float2 b0v = __half22float2(*(__half2*)&u0.y);
            float2 a1 = __half22float2(*(__half2*)&u1.x);
            float2 b1v = __half22float2(*(__half2*)&u1.y);
            float2 a2 = __half22float2(*(__half2*)&u2.x);
            float2 b2v = __half22float2(*(__half2*)&u2.y);
            float2 a3 = __half22float2(*(__half2*)&u3.x);
            float2 b3v = __half22float2(*(__half2*)&u3.y);
            acc0.x += a0.x * w0; acc0.y += a0.y * w0;
            acc0.z += b0v.x * w0; acc0.w += b0v.y * w0;
            acc1.x += a1.x * w1; acc1.y += a1.y * w1;
            acc1.z += b1v.x * w1; acc1.w += b1v.y * w1;
            acc0.x += a2.x * w2; acc0.y += a2.y * w2;
            acc0.z += b2v.x * w2; acc0.w += b2v.y * w2;
            acc1.x += a3.x * w3; acc1.y += a3.y * w3;
            acc1.z += b3v.x * w3; acc1.w += b3v.y * w3;
        }
        for (; i < end; i++) {
            int2 e0 = g_edge_s[i];
            uint2 u0 = sup[(size_t)e0.x * 32 + lane];
            float w0 = __int_as_float(e0.y);
            float2 a0 = __half22float2(*(__half2*)&u0.x);
            float2 b0v = __half22float2(*(__half2*)&u0.y);
            acc0.x += a0.x * w0; acc0.y += a0.y * w0;
            acc0.z += b0v.x * w0; acc0.w += b0v.y * w0;
        }
        float4 v;
        const float4* bb = (const float4*)b;
        float4 bv = bb[lane];
        v.x = acc0.x + acc1.x + bv.x;
        v.y = acc0.y + acc1.y + bv.y;
        v.z = acc0.z + acc1.z + bv.z;
        v.w = acc0.w + acc1.w + bv.w;
        if (do_relu) {
            v.x = fmaxf(v.x, 0.f); v.y = fmaxf(v.y, 0.f);
            v.z = fmaxf(v.z, 0.f); v.w = fmaxf(v.w, 0.f);
            *(float4*)&g_h[(size_t)d * DF + lane * 4] = v;
        }
        atomicMax(&smax[lane * 4 + 0], fenc(v.x));
        atomicMax(&smax[lane * 4 + 1], fenc(v.y));
        atomicMax(&smax[lane * 4 + 2], fenc(v.z));
        atomicMax(&smax[lane * 4 + 3], fenc(v.w));
    }
    __syncthreads();
    if (t < DF) atomicMax(&g_okey[layer * DF + t], smax[t]);
}

// ---------------- head ----------------------------------------------------

__global__ __launch_bounds__(128) void final_kernel(const float* __restrict__ lin_W,
                                                    const float* __restrict__ lin_b,
                                                    float* __restrict__ out) {
    __shared__ float lin_in[3 * DF];
    __shared__ float logits[NCLS];
    int t = threadIdx.x;
    for (int i = t; i < 3 * DF; i += 128) lin_in[i] = fdec(g_okey[i]);
    __syncthreads();
    if (t < NCLS) {
        float s = lin_b[t];
#pragma unroll 4
        for (int j = 0; j < 3 * DF; j++) s += lin_W[t * 3 * DF + j] * lin_in[j];
        logits[t] = s;
    }
    __syncthreads();
    if (t == 0) {
        float m = -3.402823466e+38f;
        for (int c = 0; c < NCLS; c++) m = fmaxf(m, logits[c]);
        float se = 0.f;
        for (int c = 0; c < NCLS; c++) se += expf(logits[c] - m);
        float lse = m + logf(se);
        for (int c = 0; c < NCLS; c++) out[c] = logits[c] - lse;
    }
}

extern "C" void kernel_launch(void* const* d_in, const int* in_sizes, int n_in,
                              void* d_out, int out_size) {
    const float* x    = (const float*)d_in[0];
    const int*   esrc = (const int*)d_in[1];
    const int*   edst = (const int*)d_in[2];
    const float* ew   = (const float*)d_in[3];
    const float* W1   = (const float*)d_in[4];
    const float* b1   = (const float*)d_in[5];
    const float* W2   = (const float*)d_in[6];
    const float* b2   = (const float*)d_in[7];
    const float* W3   = (const float*)d_in[8];
    const float* b3   = (const float*)d_in[9];
    const float* linW = (const float*)d_in[10];
    const float* linb = (const float*)d_in[11];
    float* out = (float*)d_out;

    int N = in_sizes[0] / DF;
    int E = in_sizes[1];

    static int attr_set = 0;
    if (!attr_set) {
        cudaFuncSetAttribute(gemm_kernel, cudaFuncAttributeMaxDynamicSharedMemorySize, GEMM_SMEM);
        attr_set = 1;
    }

    int eb = (E + 255) / 256;
    int gemm_blocks = (N + 127) / 128;
    int seg_blocks = (N + 7) / 8;

    init_kernel<<<(N + 256) / 256, 256>>>(N);
    hist_kernel<<<eb, 256>>>(edst, E);
    scan_kernel<<<1, 1024>>>(N);
    reorder_kernel<<<eb, 256>>>(esrc, edst, ew, E);

    gemm_kernel<<<gemm_blocks, 256, GEMM_SMEM>>>(x, W1, N, 0);
    seg_kernel<<<seg_blocks, 256>>>(b1, N, 0, 1);
    gemm_kernel<<<gemm_blocks, 256, GEMM_SMEM>>>(nullptr, W2, N, 1);
    seg_kernel<<<seg_blocks, 256>>>(b2, N, 1, 1);
    gemm_kernel<<<gemm_blocks, 256, GEMM_SMEM>>>(nullptr, W3, N, 2);
    seg_kernel<<<seg_blocks, 256>>>(b3, N, 2, 0);
    final_kernel<<<1, 128>>>(linW, linb, out);
}

// round 5
// speedup vs baseline: 2.2689x; 1.0088x over previous
#include <cuda_runtime.h>
#include <cuda_fp16.h>
#include <cuda_bf16.h>

#define DF 128
#define NMAX 50000
#define EMAX 800000
#define NCLS 10

// Scratch (allocation-free __device__ globals).
__device__ __align__(16) __half g_support[(size_t)NMAX * DF];   // fp16 gather source
__device__ __align__(16) float  g_h[(size_t)NMAX * DF];         // fp32 layer activations
__device__ __align__(16) int2   g_edge_s[EMAX];                 // sorted-by-dst (src, bits(w))
__device__ int g_cnt[NMAX + 1];
__device__ int g_rowptr[NMAX + 1];
__device__ int g_cur[NMAX + 1];
__device__ unsigned g_okey[3 * DF];

__device__ __forceinline__ unsigned fenc(float x) {
    unsigned u = __float_as_uint(x);
    return (u & 0x80000000u) ? ~u : (u | 0x80000000u);
}
__device__ __forceinline__ float fdec(unsigned k) {
    unsigned u = (k & 0x80000000u) ? (k & 0x7FFFFFFFu) : ~k;
    return __uint_as_float(u);
}
__device__ __forceinline__ unsigned f2tf(float x) {
    unsigned r;
    asm("cvt.rna.tf32.f32 %0, %1;" : "=r"(r) : "f"(x));
    return r;
}

// ---------------- sort: counting sort of edges by dst -------------------

__global__ __launch_bounds__(256) void init_kernel(int N) {
    int i = blockIdx.x * 256 + threadIdx.x;
    if (i <= N) g_cnt[i] = 0;
    if (i < 3 * DF) g_okey[i] = 0u;
}

__global__ __launch_bounds__(256) void hist_kernel(const int* __restrict__ dst, int E) {
    int e = blockIdx.x * 256 + threadIdx.x;
    if (e < E) atomicAdd(&g_cnt[dst[e]], 1);
}

__global__ __launch_bounds__(1024) void scan_kernel(int N) {
    __shared__ int part[1024];
    __shared__ int carry[1024];
    int t = threadIdx.x;
    int chunk = (N + 1023) / 1024;
    int base = t * chunk;
    int s = 0;
    for (int j = 0; j < chunk; j++) {
        int idx = base + j;
        if (idx < N) s += g_cnt[idx];
    }
    part[t] = s;
    __syncthreads();
    for (int off = 1; off < 1024; off <<= 1) {
        int v = part[t];
        int add = (t >= off) ? part[t - off] : 0;
        __syncthreads();
        part[t] = v + add;
        __syncthreads();
    }
    carry[t] = (t == 0) ? 0 : part[t - 1];
    __syncthreads();
    int run = carry[t];
    for (int j = 0; j < chunk; j++) {
        int idx = base + j;
        if (idx < N) {
            g_rowptr[idx] = run;
            g_cur[idx] = run;
            run += g_cnt[idx];
        }
    }
    if (base < N && base + chunk >= N) g_rowptr[N] = run;
}

__global__ __launch_bounds__(256) void reorder_kernel(const int* __restrict__ src,
                                                      const int* __restrict__ dst,
                                                      const float* __restrict__ w,
                                                      int E) {
    int e = blockIdx.x * 256 + threadIdx.x;
    if (e >= E) return;
    int d = dst[e];
    int pos = atomicAdd(&g_cur[d], 1);
    g_edge_s[pos] = make_int2(src[e], __float_as_int(w[e]));
}

// ---------------- GEMM: support(fp16) = Ain(fp32) @ W via TF32 mma.sync ----

#define SW 136
#define SA 68
#define GEMM_SMEM ((DF * SW + DF * SA) * (int)sizeof(unsigned))  // 104448 B

__global__ __launch_bounds__(256, 2) void gemm_kernel(const float* __restrict__ A,
                                                      const float* __restrict__ W,
                                                      int N, int use_gh) {
    extern __shared__ unsigned smem_u[];
    unsigned* Ws = smem_u;            // [128][136] tf32
    unsigned* As = smem_u + DF * SW;  // [128][68] tf32 (k-chunk of 64)
    const float* Ain = use_gh ? g_h : A;

    int t = threadIdx.x;
    int lane = t & 31;
    int wrp = t >> 5;
    int wm = wrp >> 1;
    int wn = wrp & 1;
    int r0 = blockIdx.x * 128;

    for (int i = t; i < DF * DF / 4; i += 256) {
        int k = i >> 5;
        int n4 = (i & 31) * 4;
        float4 wv = *(const float4*)&W[k * DF + n4];
        Ws[k * SW + n4 + 0] = f2tf(wv.x);
        Ws[k * SW + n4 + 1] = f2tf(wv.y);
        Ws[k * SW + n4 + 2] = f2tf(wv.z);
        Ws[k * SW + n4 + 3] = f2tf(wv.w);
    }

    float acc[2][8][4];
#pragma unroll
    for (int mt = 0; mt < 2; mt++)
#pragma unroll
        for (int nt = 0; nt < 8; nt++)
#pragma unroll
            for (int r = 0; r < 4; r++) acc[mt][nt][r] = 0.f;

    int gid = lane >> 2;
    int tig = lane & 3;

    for (int kc = 0; kc < 2; kc++) {
        __syncthreads();
        for (int i = t; i < DF * 16; i += 256) {
            int row = i >> 4;
            int k4 = (i & 15) * 4;
            int gr = r0 + row;
            float4 av = make_float4(0.f, 0.f, 0.f, 0.f);
            if (gr < N) av = *(const float4*)&Ain[(size_t)gr * DF + kc * 64 + k4];
            As[row * SA + k4 + 0] = f2tf(av.x);
            As[row * SA + k4 + 1] = f2tf(av.y);
            As[row * SA + k4 + 2] = f2tf(av.z);
            As[row * SA + k4 + 3] = f2tf(av.w);
        }
        __syncthreads();

#pragma unroll
        for (int kk = 0; kk < 8; kk++) {
            int kb = kk * 8;
            int kg = kc * 64 + kb;
            unsigned afr[2][4];
#pragma unroll
            for (int mt = 0; mt < 2; mt++) {
                int arow = wm * 32 + mt * 16 + gid;
                afr[mt][0] = As[arow * SA + kb + tig];
                afr[mt][1] = As[(arow + 8) * SA + kb + tig];
                afr[mt][2] = As[arow * SA + kb + tig + 4];
                afr[mt][3] = As[(arow + 8) * SA + kb + tig + 4];
            }
#pragma unroll
            for (int nt = 0; nt < 8; nt++) {
                int ncol = wn * 64 + nt * 8 + gid;
                unsigned b0 = Ws[(kg + tig) * SW + ncol];
                unsigned b1 = Ws[(kg + tig + 4) * SW + ncol];
#pragma unroll
                for (int mt = 0; mt < 2; mt++) {
                    asm volatile(
                        "mma.sync.aligned.m16n8k8.row.col.f32.tf32.tf32.f32 "
                        "{%0,%1,%2,%3}, {%4,%5,%6,%7}, {%8,%9}, {%0,%1,%2,%3};"
                        : "+f"(acc[mt][nt][0]), "+f"(acc[mt][nt][1]),
                          "+f"(acc[mt][nt][2]), "+f"(acc[mt][nt][3])
                        : "r"(afr[mt][0]), "r"(afr[mt][1]),
                          "r"(afr[mt][2]), "r"(afr[mt][3]),
                          "r"(b0), "r"(b1));
                }
            }
        }
    }

#pragma unroll
    for (int mt = 0; mt < 2; mt++) {
#pragma unroll
        for (int nt = 0; nt < 8; nt++) {
            int row = r0 + wm * 32 + mt * 16 + gid;
            int col = wn * 64 + nt * 8 + 2 * tig;
            if (row < N)
                *(__half2*)&g_support[(size_t)row * DF + col] =
                    __floats2half2_rn(acc[mt][nt][0], acc[mt][nt][1]);
            if (row + 8 < N)
                *(__half2*)&g_support[(size_t)(row + 8) * DF + col] =
                    __floats2half2_rn(acc[mt][nt][2], acc[mt][nt][3]);
        }
    }
}

// ---------------- segment-sum + bias (+relu, h write) + column max --------
// One warp per dst row. Descriptors for the whole row loaded with ONE
// coalesced lane-parallel LDG, broadcast via shfl; gathers issued 8-wide.

__device__ __forceinline__ void edge_fma(float4& a, const uint2 u, const float w) {
    float2 lo = __half22float2(*(const __half2*)&u.x);
    float2 hi = __half22float2(*(const __half2*)&u.y);
    a.x += lo.x * w; a.y += lo.y * w;
    a.z += hi.x * w; a.w += hi.y * w;
}

__global__ __launch_bounds__(256) void seg_kernel(const float* __restrict__ b,
                                                  int N, int layer, int do_relu) {
    __shared__ unsigned smax[DF];
    int t = threadIdx.x;
    int lane = t & 31;
    int wrp = t >> 5;
    if (t < DF) smax[t] = 0u;
    __syncthreads();

    int d = blockIdx.x * 8 + wrp;
    if (d < N) {
        int beg = g_rowptr[d];
        int end = g_rowptr[d + 1];
        const uint2* sup = (const uint2*)g_support;

        float4 acc0 = make_float4(0.f, 0.f, 0.f, 0.f);
        float4 acc1 = make_float4(0.f, 0.f, 0.f, 0.f);

        for (int base = beg; base < end; base += 32) {
            int m = end - base;
            if (m > 32) m = 32;
            // One coalesced warp-load covers all descriptors of this batch.
            int2 dsc = make_int2(0, 0);
            if (lane < m) dsc = g_edge_s[base + lane];

            int j = 0;
            for (; j + 8 <= m; j += 8) {
                int s0 = __shfl_sync(0xffffffffu, dsc.x, j + 0);
                int s1 = __shfl_sync(0xffffffffu, dsc.x, j + 1);
                int s2 = __shfl_sync(0xffffffffu, dsc.x, j + 2);
                int s3 = __shfl_sync(0xffffffffu, dsc.x, j + 3);
                int s4 = __shfl_sync(0xffffffffu, dsc.x, j + 4);
                int s5 = __shfl_sync(0xffffffffu, dsc.x, j + 5);
                int s6 = __shfl_sync(0xffffffffu, dsc.x, j + 6);
                int s7 = __shfl_sync(0xffffffffu, dsc.x, j + 7);
                float w0 = __int_as_float(__shfl_sync(0xffffffffu, dsc.y, j + 0));
                float w1 = __int_as_float(__shfl_sync(0xffffffffu, dsc.y, j + 1));
                float w2 = __int_as_float(__shfl_sync(0xffffffffu, dsc.y, j + 2));
                float w3 = __int_as_float(__shfl_sync(0xffffffffu, dsc.y, j + 3));
                float w4 = __int_as_float(__shfl_sync(0xffffffffu, dsc.y, j + 4));
                float w5 = __int_as_float(__shfl_sync(0xffffffffu, dsc.y, j + 5));
                float w6 = __int_as_float(__shfl_sync(0xffffffffu, dsc.y, j + 6));
                float w7 = __int_as_float(__shfl_sync(0xffffffffu, dsc.y, j + 7));
                // 8 independent gathers in flight.
                uint2 u0 = sup[(size_t)s0 * 32 + lane];
                uint2 u1 = sup[(size_t)s1 * 32 + lane];
                uint2 u2 = sup[(size_t)s2 * 32 + lane];
                uint2 u3 = sup[(size_t)s3 * 32 + lane];
                uint2 u4 = sup[(size_t)s4 * 32 + lane];
                uint2 u5 = sup[(size_t)s5 * 32 + lane];
                uint2 u6 = sup[(size_t)s6 * 32 + lane];
                uint2 u7 = sup[(size_t)s7 * 32 + lane];
                edge_fma(acc0, u0, w0);
                edge_fma(acc1, u1, w1);
                edge_fma(acc0, u2, w2);
                edge_fma(acc1, u3, w3);
                edge_fma(acc0, u4, w4);
                edge_fma(acc1, u5, w5);
                edge_fma(acc0, u6, w6);
                edge_fma(acc1, u7, w7);
            }
            for (; j + 2 <= m; j += 2) {
                int s0 = __shfl_sync(0xffffffffu, dsc.x, j + 0);
                int s1 = __shfl_sync(0xffffffffu, dsc.x, j + 1);
                float w0 = __int_as_float(__shfl_sync(0xffffffffu, dsc.y, j + 0));
                float w1 = __int_as_float(__shfl_sync(0xffffffffu, dsc.y, j + 1));
                uint2 u0 = sup[(size_t)s0 * 32 + lane];
                uint2 u1 = sup[(size_t)s1 * 32 + lane];
                edge_fma(acc0, u0, w0);
                edge_fma(acc1, u1, w1);
            }
            if (j < m) {
                int s0 = __shfl_sync(0xffffffffu, dsc.x, j);
                float w0 = __int_as_float(__shfl_sync(0xffffffffu, dsc.y, j));
                uint2 u0 = sup[(size_t)s0 * 32 + lane];
                edge_fma(acc0, u0, w0);
            }
        }

        float4 v;
        const float4* bb = (const float4*)b;
        float4 bv = bb[lane];
        v.x = acc0.x + acc1.x + bv.x;
        v.y = acc0.y + acc1.y + bv.y;
        v.z = acc0.z + acc1.z + bv.z;
        v.w = acc0.w + acc1.w + bv.w;
        if (do_relu) {
            v.x = fmaxf(v.x, 0.f); v.y = fmaxf(v.y, 0.f);
            v.z = fmaxf(v.z, 0.f); v.w = fmaxf(v.w, 0.f);
            *(float4*)&g_h[(size_t)d * DF + lane * 4] = v;
        }
        atomicMax(&smax[lane * 4 + 0], fenc(v.x));
        atomicMax(&smax[lane * 4 + 1], fenc(v.y));
        atomicMax(&smax[lane * 4 + 2], fenc(v.z));
        atomicMax(&smax[lane * 4 + 3], fenc(v.w));
    }
    __syncthreads();
    if (t < DF) atomicMax(&g_okey[layer * DF + t], smax[t]);
}

// ---------------- head ----------------------------------------------------

__global__ __launch_bounds__(128) void final_kernel(const float* __restrict__ lin_W,
                                                    const float* __restrict__ lin_b,
                                                    float* __restrict__ out) {
    __shared__ float lin_in[3 * DF];
    __shared__ float logits[NCLS];
    int t = threadIdx.x;
    for (int i = t; i < 3 * DF; i += 128) lin_in[i] = fdec(g_okey[i]);
    __syncthreads();
    if (t < NCLS) {
        float s = lin_b[t];
#pragma unroll 4
        for (int j = 0; j < 3 * DF; j++) s += lin_W[t * 3 * DF + j] * lin_in[j];
        logits[t] = s;
    }
    __syncthreads();
    if (t == 0) {
        float m = -3.402823466e+38f;
        for (int c = 0; c < NCLS; c++) m = fmaxf(m, logits[c]);
        float se = 0.f;
        for (int c = 0; c < NCLS; c++) se += expf(logits[c] - m);
        float lse = m + logf(se);
        for (int c = 0; c < NCLS; c++) out[c] = logits[c] - lse;
    }
}

extern "C" void kernel_launch(void* const* d_in, const int* in_sizes, int n_in,
                              void* d_out, int out_size) {
    const float* x    = (const float*)d_in[0];
    const int*   esrc = (const int*)d_in[1];
    const int*   edst = (const int*)d_in[2];
    const float* ew   = (const float*)d_in[3];
    const float* W1   = (const float*)d_in[4];
    const float* b1   = (const float*)d_in[5];
    const float* W2   = (const float*)d_in[6];
    const float* b2   = (const float*)d_in[7];
    const float* W3   = (const float*)d_in[8];
    const float* b3   = (const float*)d_in[9];
    const float* linW = (const float*)d_in[10];
    const float* linb = (const float*)d_in[11];
    float* out = (float*)d_out;

    int N = in_sizes[0] / DF;
    int E = in_sizes[1];

    static int attr_set = 0;
    if (!attr_set) {
        cudaFuncSetAttribute(gemm_kernel, cudaFuncAttributeMaxDynamicSharedMemorySize, GEMM_SMEM);
        attr_set = 1;
    }

    int eb = (E + 255) / 256;
    int gemm_blocks = (N + 127) / 128;
    int seg_blocks = (N + 7) / 8;

    init_kernel<<<(N + 256) / 256, 256>>>(N);
    hist_kernel<<<eb, 256>>>(edst, E);
    scan_kernel<<<1, 1024>>>(N);
    reorder_kernel<<<eb, 256>>>(esrc, edst, ew, E);

    gemm_kernel<<<gemm_blocks, 256, GEMM_SMEM>>>(x, W1, N, 0);
    seg_kernel<<<seg_blocks, 256>>>(b1, N, 0, 1);
    gemm_kernel<<<gemm_blocks, 256, GEMM_SMEM>>>(nullptr, W2, N, 1);
    seg_kernel<<<seg_blocks, 256>>>(b2, N, 1, 1);
    gemm_kernel<<<gemm_blocks, 256, GEMM_SMEM>>>(nullptr, W3, N, 2);
    seg_kernel<<<seg_blocks, 256>>>(b3, N, 2, 0);
    final_kernel<<<1, 128>>>(linW, linb, out);
}